// round 1
// baseline (speedup 1.0000x reference)
#include <cuda_runtime.h>
#include <cuda_bf16.h>
#include <cstdint>

// Problem constants
#define B_ 8
#define L_ 2048
#define DM_ 192
#define DI_ 384
#define N_ 16
#define R_ 12
#define M_ (B_ * L_)           // 16384 rows
#define NXZ_ (2 * DI_)          // 768
#define NC_ (R_ + 2 * N_)       // 44

// ---------------- scratch (static device allocations; no cudaMalloc) -------
__device__ float g_u[M_ * DI_];       // 25.2 MB
__device__ float g_z[M_ * DI_];       // 25.2 MB
__device__ float g_delta[M_ * DI_];   // 25.2 MB
__device__ float g_Bs[M_ * N_];       // 2.1 MB
__device__ float g_Cs[M_ * N_];       // 2.1 MB
__device__ float g_y[M_ * DI_];       // 25.2 MB

// ============================================================================
// K1: xz = silu(x @ W_in^T), split into u / z.
//   X: [M, 192], W: [768, 192], U/Z: [M, 384]
//   64x64 tile, BK=16, 256 threads, 4x4 per-thread microtile.
// ============================================================================
#define K1_BM 64
#define K1_BN 64
#define K1_BK 16

__global__ __launch_bounds__(256) void k1_gemm_silu(
    const float* __restrict__ X, const float* __restrict__ W,
    float* __restrict__ U, float* __restrict__ Z)
{
    __shared__ float As[K1_BK][K1_BM];
    __shared__ float Ws[K1_BK][K1_BN];

    const int tid = threadIdx.x;
    const int bm = blockIdx.x * K1_BM;
    const int bn = blockIdx.y * K1_BN;

    const int tx = tid & 15;   // n direction (x4)
    const int ty = tid >> 4;   // m direction (x4)

    const int lrow = tid >> 2;          // 0..63
    const int lcol = (tid & 3) * 4;     // 0,4,8,12

    float acc[4][4];
#pragma unroll
    for (int i = 0; i < 4; i++)
#pragma unroll
        for (int j = 0; j < 4; j++) acc[i][j] = 0.f;

    for (int k0 = 0; k0 < DM_; k0 += K1_BK) {
        float4 av = *(const float4*)&X[(size_t)(bm + lrow) * DM_ + k0 + lcol];
        float4 wv = *(const float4*)&W[(size_t)(bn + lrow) * DM_ + k0 + lcol];
        As[lcol + 0][lrow] = av.x; As[lcol + 1][lrow] = av.y;
        As[lcol + 2][lrow] = av.z; As[lcol + 3][lrow] = av.w;
        Ws[lcol + 0][lrow] = wv.x; Ws[lcol + 1][lrow] = wv.y;
        Ws[lcol + 2][lrow] = wv.z; Ws[lcol + 3][lrow] = wv.w;
        __syncthreads();

#pragma unroll
        for (int kk = 0; kk < K1_BK; kk++) {
            float a[4], w[4];
#pragma unroll
            for (int i = 0; i < 4; i++) a[i] = As[kk][ty * 4 + i];
#pragma unroll
            for (int j = 0; j < 4; j++) w[j] = Ws[kk][tx * 4 + j];
#pragma unroll
            for (int i = 0; i < 4; i++)
#pragma unroll
                for (int j = 0; j < 4; j++)
                    acc[i][j] = fmaf(a[i], w[j], acc[i][j]);
        }
        __syncthreads();
    }

    const int ncol = bn + tx * 4;           // first of 4 consecutive cols
#pragma unroll
    for (int i = 0; i < 4; i++) {
        const int m = bm + ty * 4 + i;
        float4 o;
        float c0 = acc[i][0], c1 = acc[i][1], c2 = acc[i][2], c3 = acc[i][3];
        o.x = c0 / (1.f + __expf(-c0));
        o.y = c1 / (1.f + __expf(-c1));
        o.z = c2 / (1.f + __expf(-c2));
        o.w = c3 / (1.f + __expf(-c3));
        if (ncol < DI_) {
            *(float4*)&U[(size_t)m * DI_ + ncol] = o;
        } else {
            *(float4*)&Z[(size_t)m * DI_ + (ncol - DI_)] = o;
        }
    }
}

// ============================================================================
// K2: per 16-row tile:
//   dbl[r, 0:44] = u_row . x_proj_w[c]
//   Bs = dbl[12:28], Cs = dbl[28:44]
//   delta[r, d] = softplus( dbl[r,0:12] . dt_proj_w[d] + dt_proj_b[d] )
// ============================================================================
#define K2_ROWS 16

__device__ __forceinline__ float softplusf(float x) {
    return (x > 20.f) ? x : log1pf(__expf(x));
}

__global__ __launch_bounds__(256) void k2_proj(
    const float* __restrict__ U, const float* __restrict__ XPW,
    const float* __restrict__ DTW, const float* __restrict__ DTB,
    float* __restrict__ Delta, float* __restrict__ Bs, float* __restrict__ Cs)
{
    __shared__ float su[K2_ROWS][DI_];        // 24 KB
    __shared__ float sdbl[K2_ROWS][NC_];      // 2.8 KB
    __shared__ float sdtw[DI_ * R_];          // 18 KB
    __shared__ float sdtb[DI_];               // 1.5 KB

    const int tid = threadIdx.x;
    const int row0 = blockIdx.x * K2_ROWS;

    // stage u rows
    for (int i = tid; i < K2_ROWS * DI_; i += 256) {
        int r = i / DI_, k = i % DI_;
        su[r][k] = U[(size_t)(row0 + r) * DI_ + k];
    }
    for (int i = tid; i < DI_ * R_; i += 256) sdtw[i] = DTW[i];
    for (int i = tid; i < DI_; i += 256) sdtb[i] = DTB[i];
    __syncthreads();

    // dbl = u @ XPW^T  (16 x 44 outputs)
    for (int o = tid; o < K2_ROWS * NC_; o += 256) {
        int r = o / NC_, c = o % NC_;
        const float* wr = XPW + (size_t)c * DI_;
        float acc = 0.f;
#pragma unroll 4
        for (int k = 0; k < DI_; k += 4) {
            acc = fmaf(su[r][k + 0], wr[k + 0], acc);
            acc = fmaf(su[r][k + 1], wr[k + 1], acc);
            acc = fmaf(su[r][k + 2], wr[k + 2], acc);
            acc = fmaf(su[r][k + 3], wr[k + 3], acc);
        }
        sdbl[r][c] = acc;
    }
    __syncthreads();

    // scatter B / C
    for (int o = tid; o < K2_ROWS * 2 * N_; o += 256) {
        int r = o / (2 * N_), c = o % (2 * N_);
        float v = sdbl[r][R_ + c];
        if (c < N_) Bs[(size_t)(row0 + r) * N_ + c] = v;
        else        Cs[(size_t)(row0 + r) * N_ + (c - N_)] = v;
    }

    // delta = softplus(dbl[:, :12] @ DTW^T + DTB)
    for (int o = tid; o < K2_ROWS * DI_; o += 256) {
        int r = o / DI_, d = o % DI_;
        float acc = sdtb[d];
        const float* wd = &sdtw[d * R_];
#pragma unroll
        for (int j = 0; j < R_; j++) acc = fmaf(sdbl[r][j], wd[j], acc);
        Delta[(size_t)(row0 + r) * DI_ + d] = softplusf(acc);
    }
}

// ============================================================================
// K3: selective scan. 16 lanes per (b,d) group over n; 2 groups per warp.
//   h_n <- exp(delta*A_n) * h_n + delta*u*B_n ;  y = sum_n h_n*C_n + D_d*u
// ============================================================================
__global__ __launch_bounds__(256) void k3_scan(
    const float* __restrict__ Delta, const float* __restrict__ U,
    const float* __restrict__ Bsg, const float* __restrict__ Csg,
    const float* __restrict__ A_logs, const float* __restrict__ Ds,
    float* __restrict__ Y)
{
    const int tid = threadIdx.x;
    const int grp = (blockIdx.x * blockDim.x + tid) >> 4;   // (b,d) group
    const int n = tid & 15;
    const int b = grp / DI_;
    const int d = grp - b * DI_;

    const float A = -__expf(A_logs[d * N_ + n]);
    const float Dd = Ds[d];

    const float* dptr = Delta + (size_t)b * L_ * DI_ + d;
    const float* uptr = U     + (size_t)b * L_ * DI_ + d;
    const float* bptr = Bsg   + (size_t)b * L_ * N_ + n;
    const float* cptr = Csg   + (size_t)b * L_ * N_ + n;
    float* yptr       = Y     + (size_t)b * L_ * DI_ + d;

    float h = 0.f;
#pragma unroll 4
    for (int t = 0; t < L_; t++) {
        const float delta = dptr[(size_t)t * DI_];
        const float u     = uptr[(size_t)t * DI_];
        const float Bv    = bptr[(size_t)t * N_];
        const float Cv    = cptr[(size_t)t * N_];
        const float dA = __expf(delta * A);
        h = fmaf(dA, h, delta * u * Bv);
        float y = h * Cv;
        y += __shfl_xor_sync(0xffffffffu, y, 8, 16);
        y += __shfl_xor_sync(0xffffffffu, y, 4, 16);
        y += __shfl_xor_sync(0xffffffffu, y, 2, 16);
        y += __shfl_xor_sync(0xffffffffu, y, 1, 16);
        if (n == 0) yptr[(size_t)t * DI_] = fmaf(Dd, u, y);
    }
}

// ============================================================================
// K4: LayerNorm(y) * z, then out = yln @ W_out^T.
//   4 rows per block (warp-per-row LN), then 768 outputs across 128 threads.
// ============================================================================
__global__ __launch_bounds__(128) void k4_ln_gemm(
    const float* __restrict__ Y, const float* __restrict__ Zg,
    const float* __restrict__ gamma, const float* __restrict__ beta,
    const float* __restrict__ Wout, float* __restrict__ Out)
{
    __shared__ float sy[4][DI_];   // 6 KB

    const int tid = threadIdx.x;
    const int warp = tid >> 5, lane = tid & 31;
    const int row = blockIdx.x * 4 + warp;

    const float* yr = Y  + (size_t)row * DI_;
    const float* zr = Zg + (size_t)row * DI_;

    float v[12];
    float sum = 0.f, sq = 0.f;
#pragma unroll
    for (int i = 0; i < 12; i++) {
        float t = yr[lane + i * 32];
        v[i] = t; sum += t; sq = fmaf(t, t, sq);
    }
#pragma unroll
    for (int o = 16; o; o >>= 1) {
        sum += __shfl_xor_sync(0xffffffffu, sum, o);
        sq  += __shfl_xor_sync(0xffffffffu, sq, o);
    }
    const float mu = sum * (1.f / DI_);
    const float var = sq * (1.f / DI_) - mu * mu;
    const float rs = rsqrtf(var + 1e-5f);
#pragma unroll
    for (int i = 0; i < 12; i++) {
        int k = lane + i * 32;
        sy[warp][k] = fmaf((v[i] - mu) * rs, gamma[k], beta[k]) * zr[k];
    }
    __syncthreads();

    // GEMM: 4 rows x 192 cols = 768 outputs, 6 per thread
#pragma unroll
    for (int oi = 0; oi < 6; oi++) {
        const int o = tid + oi * 128;
        const int r = o / DM_, m = o % DM_;
        const float4* w4 = (const float4*)(Wout + (size_t)m * DI_);
        const float4* s4 = (const float4*)(&sy[r][0]);
        float acc = 0.f;
#pragma unroll 4
        for (int k = 0; k < DI_ / 4; k++) {
            float4 a = s4[k], b = w4[k];
            acc = fmaf(a.x, b.x, acc);
            acc = fmaf(a.y, b.y, acc);
            acc = fmaf(a.z, b.z, acc);
            acc = fmaf(a.w, b.w, acc);
        }
        Out[(size_t)(blockIdx.x * 4 + r) * DM_ + m] = acc;
    }
}

// ============================================================================
extern "C" void kernel_launch(void* const* d_in, const int* in_sizes, int n_in,
                              void* d_out, int out_size)
{
    const float* x         = (const float*)d_in[0];
    const float* W_in      = (const float*)d_in[1];
    const float* x_proj_w  = (const float*)d_in[2];
    const float* dt_proj_w = (const float*)d_in[3];
    const float* dt_proj_b = (const float*)d_in[4];
    const float* A_logs    = (const float*)d_in[5];
    const float* Ds        = (const float*)d_in[6];
    const float* ln_gamma  = (const float*)d_in[7];
    const float* ln_beta   = (const float*)d_in[8];
    const float* W_out     = (const float*)d_in[9];
    float* out = (float*)d_out;

    float *u, *z, *delta, *bs, *cs, *y;
    cudaGetSymbolAddress((void**)&u, g_u);
    cudaGetSymbolAddress((void**)&z, g_z);
    cudaGetSymbolAddress((void**)&delta, g_delta);
    cudaGetSymbolAddress((void**)&bs, g_Bs);
    cudaGetSymbolAddress((void**)&cs, g_Cs);
    cudaGetSymbolAddress((void**)&y, g_y);

    dim3 g1(M_ / K1_BM, NXZ_ / K1_BN);          // 256 x 12
    k1_gemm_silu<<<g1, 256>>>(x, W_in, u, z);

    k2_proj<<<M_ / K2_ROWS, 256>>>(u, x_proj_w, dt_proj_w, dt_proj_b,
                                   delta, bs, cs);

    k3_scan<<<(B_ * DI_ * 16) / 256, 256>>>(delta, u, bs, cs, A_logs, Ds, y);

    k4_ln_gemm<<<M_ / 4, 128>>>(y, z, ln_gamma, ln_beta, W_out, out);
}

// round 2
// speedup vs baseline: 3.1041x; 3.1041x over previous
#include <cuda_runtime.h>
#include <cuda_bf16.h>
#include <cstdint>

// Problem constants
#define B_ 8
#define L_ 2048
#define DM_ 192
#define DI_ 384
#define N_ 16
#define R_ 12
#define M_ (B_ * L_)           // 16384 rows
#define NXZ_ (2 * DI_)          // 768
#define NC_ (R_ + 2 * N_)       // 44

// ---------------- scratch (static device allocations; no cudaMalloc) -------
__device__ float g_u[M_ * DI_];
__device__ float g_z[M_ * DI_];
__device__ float g_delta[M_ * DI_];
__device__ float g_Bs[M_ * N_];
__device__ float g_Cs[M_ * N_];
__device__ float g_y[M_ * DI_];
__device__ float g_yln[M_ * DI_];

// ============================================================================
// K1: xz = silu(x @ W_in^T), split into u / z.
// ============================================================================
#define K1_BM 64
#define K1_BN 64
#define K1_BK 16

__global__ __launch_bounds__(256) void k1_gemm_silu(
    const float* __restrict__ X, const float* __restrict__ W,
    float* __restrict__ U, float* __restrict__ Z)
{
    __shared__ float As[K1_BK][K1_BM];
    __shared__ float Ws[K1_BK][K1_BN];

    const int tid = threadIdx.x;
    const int bm = blockIdx.x * K1_BM;
    const int bn = blockIdx.y * K1_BN;

    const int tx = tid & 15;
    const int ty = tid >> 4;

    const int lrow = tid >> 2;
    const int lcol = (tid & 3) * 4;

    float acc[4][4];
#pragma unroll
    for (int i = 0; i < 4; i++)
#pragma unroll
        for (int j = 0; j < 4; j++) acc[i][j] = 0.f;

    for (int k0 = 0; k0 < DM_; k0 += K1_BK) {
        float4 av = *(const float4*)&X[(size_t)(bm + lrow) * DM_ + k0 + lcol];
        float4 wv = *(const float4*)&W[(size_t)(bn + lrow) * DM_ + k0 + lcol];
        As[lcol + 0][lrow] = av.x; As[lcol + 1][lrow] = av.y;
        As[lcol + 2][lrow] = av.z; As[lcol + 3][lrow] = av.w;
        Ws[lcol + 0][lrow] = wv.x; Ws[lcol + 1][lrow] = wv.y;
        Ws[lcol + 2][lrow] = wv.z; Ws[lcol + 3][lrow] = wv.w;
        __syncthreads();

#pragma unroll
        for (int kk = 0; kk < K1_BK; kk++) {
            float a[4], w[4];
#pragma unroll
            for (int i = 0; i < 4; i++) a[i] = As[kk][ty * 4 + i];
#pragma unroll
            for (int j = 0; j < 4; j++) w[j] = Ws[kk][tx * 4 + j];
#pragma unroll
            for (int i = 0; i < 4; i++)
#pragma unroll
                for (int j = 0; j < 4; j++)
                    acc[i][j] = fmaf(a[i], w[j], acc[i][j]);
        }
        __syncthreads();
    }

    const int ncol = bn + tx * 4;
#pragma unroll
    for (int i = 0; i < 4; i++) {
        const int m = bm + ty * 4 + i;
        float4 o;
        float c0 = acc[i][0], c1 = acc[i][1], c2 = acc[i][2], c3 = acc[i][3];
        o.x = c0 / (1.f + __expf(-c0));
        o.y = c1 / (1.f + __expf(-c1));
        o.z = c2 / (1.f + __expf(-c2));
        o.w = c3 / (1.f + __expf(-c3));
        if (ncol < DI_) {
            *(float4*)&U[(size_t)m * DI_ + ncol] = o;
        } else {
            *(float4*)&Z[(size_t)m * DI_ + (ncol - DI_)] = o;
        }
    }
}

// ============================================================================
// K2: warp-per-column projection. Coalesced XPW reads, shfl reduction.
// ============================================================================
#define K2_ROWS 16

__device__ __forceinline__ float softplusf(float x) {
    return (x > 20.f) ? x : log1pf(__expf(x));
}

__global__ __launch_bounds__(256) void k2_proj(
    const float* __restrict__ U, const float* __restrict__ XPW,
    const float* __restrict__ DTW, const float* __restrict__ DTB,
    float* __restrict__ Delta, float* __restrict__ Bs, float* __restrict__ Cs)
{
    __shared__ float su[K2_ROWS][DI_];        // 24 KB
    __shared__ float sdbl[K2_ROWS][NC_];
    __shared__ float sdtw[DI_ * R_];          // 18 KB
    __shared__ float sdtb[DI_];

    const int tid = threadIdx.x;
    const int row0 = blockIdx.x * K2_ROWS;
    const int warp = tid >> 5, lane = tid & 31;

    for (int i = tid; i < K2_ROWS * DI_; i += 256) {
        int r = i / DI_, k = i % DI_;
        su[r][k] = U[(size_t)(row0 + r) * DI_ + k];
    }
    for (int i = tid; i < DI_ * R_; i += 256) sdtw[i] = DTW[i];
    for (int i = tid; i < DI_; i += 256) sdtb[i] = DTB[i];
    __syncthreads();

    // dbl = u @ XPW^T : warp w handles column c, lanes split K (coalesced)
    for (int c = warp; c < NC_; c += 8) {
        const float* wr = XPW + (size_t)c * DI_;
        float acc[K2_ROWS];
#pragma unroll
        for (int r = 0; r < K2_ROWS; r++) acc[r] = 0.f;
#pragma unroll
        for (int i = 0; i < DI_ / 32; i++) {
            const int k = i * 32 + lane;
            const float w = wr[k];
#pragma unroll
            for (int r = 0; r < K2_ROWS; r++)
                acc[r] = fmaf(su[r][k], w, acc[r]);
        }
#pragma unroll
        for (int r = 0; r < K2_ROWS; r++) {
            float v = acc[r];
#pragma unroll
            for (int o = 16; o; o >>= 1) v += __shfl_xor_sync(0xffffffffu, v, o);
            if (lane == 0) sdbl[r][c] = v;
        }
    }
    __syncthreads();

    // scatter B / C (coalesced-ish small writes)
    for (int o = tid; o < K2_ROWS * 2 * N_; o += 256) {
        int r = o / (2 * N_), c = o % (2 * N_);
        float v = sdbl[r][R_ + c];
        if (c < N_) Bs[(size_t)(row0 + r) * N_ + c] = v;
        else        Cs[(size_t)(row0 + r) * N_ + (c - N_)] = v;
    }

    // delta = softplus(dbl[:, :12] @ DTW^T + DTB)
    for (int o = tid; o < K2_ROWS * DI_; o += 256) {
        int r = o / DI_, d = o % DI_;
        float acc = sdtb[d];
        const float* wd = &sdtw[d * R_];
#pragma unroll
        for (int j = 0; j < R_; j++) acc = fmaf(sdbl[r][j], wd[j], acc);
        Delta[(size_t)(row0 + r) * DI_ + d] = softplusf(acc);
    }
}

// ============================================================================
// K3: selective scan. 16 lanes per (b,d) group over n.
// ============================================================================
__global__ __launch_bounds__(256) void k3_scan(
    const float* __restrict__ Delta, const float* __restrict__ U,
    const float* __restrict__ Bsg, const float* __restrict__ Csg,
    const float* __restrict__ A_logs, const float* __restrict__ Ds,
    float* __restrict__ Y)
{
    const int tid = threadIdx.x;
    const int grp = (blockIdx.x * blockDim.x + tid) >> 4;
    const int n = tid & 15;
    const int b = grp / DI_;
    const int d = grp - b * DI_;

    const float A = -__expf(A_logs[d * N_ + n]);
    const float Dd = Ds[d];

    const float* dptr = Delta + (size_t)b * L_ * DI_ + d;
    const float* uptr = U     + (size_t)b * L_ * DI_ + d;
    const float* bptr = Bsg   + (size_t)b * L_ * N_ + n;
    const float* cptr = Csg   + (size_t)b * L_ * N_ + n;
    float* yptr       = Y     + (size_t)b * L_ * DI_ + d;

    float h = 0.f;
#pragma unroll 4
    for (int t = 0; t < L_; t++) {
        const float delta = dptr[(size_t)t * DI_];
        const float u     = uptr[(size_t)t * DI_];
        const float Bv    = bptr[(size_t)t * N_];
        const float Cv    = cptr[(size_t)t * N_];
        const float dA = __expf(delta * A);
        h = fmaf(dA, h, delta * u * Bv);
        float y = h * Cv;
        y += __shfl_xor_sync(0xffffffffu, y, 8, 16);
        y += __shfl_xor_sync(0xffffffffu, y, 4, 16);
        y += __shfl_xor_sync(0xffffffffu, y, 2, 16);
        y += __shfl_xor_sync(0xffffffffu, y, 1, 16);
        if (n == 0) yptr[(size_t)t * DI_] = fmaf(Dd, u, y);
    }
}

// ============================================================================
// K4a: yln = (LayerNorm(y) * gamma + beta) * z   (memory-bound, warp/row)
// ============================================================================
__global__ __launch_bounds__(256) void k4a_ln(
    const float* __restrict__ Y, const float* __restrict__ Zg,
    const float* __restrict__ gamma, const float* __restrict__ beta,
    float* __restrict__ Yln)
{
    const int tid = threadIdx.x;
    const int warp = tid >> 5, lane = tid & 31;
    const int row = blockIdx.x * 8 + warp;

    const float* yr = Y   + (size_t)row * DI_;
    const float* zr = Zg  + (size_t)row * DI_;
    float* outr     = Yln + (size_t)row * DI_;

    float v[12];
    float sum = 0.f, sq = 0.f;
#pragma unroll
    for (int i = 0; i < 12; i++) {
        float t = yr[lane + i * 32];
        v[i] = t; sum += t; sq = fmaf(t, t, sq);
    }
#pragma unroll
    for (int o = 16; o; o >>= 1) {
        sum += __shfl_xor_sync(0xffffffffu, sum, o);
        sq  += __shfl_xor_sync(0xffffffffu, sq, o);
    }
    const float mu = sum * (1.f / DI_);
    const float var = sq * (1.f / DI_) - mu * mu;
    const float rs = rsqrtf(var + 1e-5f);
#pragma unroll
    for (int i = 0; i < 12; i++) {
        int k = lane + i * 32;
        outr[k] = fmaf((v[i] - mu) * rs, gamma[k], beta[k]) * zr[k];
    }
}

// ============================================================================
// K4b: Out = Yln @ W_out^T.  Tiled GEMM, M=16384, N=192, K=384.
// ============================================================================
__global__ __launch_bounds__(256) void k4b_gemm(
    const float* __restrict__ Xm, const float* __restrict__ W,
    float* __restrict__ Out)
{
    __shared__ float As[K1_BK][K1_BM];
    __shared__ float Ws[K1_BK][K1_BN];

    const int tid = threadIdx.x;
    const int bm = blockIdx.x * K1_BM;
    const int bn = blockIdx.y * K1_BN;

    const int tx = tid & 15;
    const int ty = tid >> 4;

    const int lrow = tid >> 2;
    const int lcol = (tid & 3) * 4;

    float acc[4][4];
#pragma unroll
    for (int i = 0; i < 4; i++)
#pragma unroll
        for (int j = 0; j < 4; j++) acc[i][j] = 0.f;

    for (int k0 = 0; k0 < DI_; k0 += K1_BK) {
        float4 av = *(const float4*)&Xm[(size_t)(bm + lrow) * DI_ + k0 + lcol];
        float4 wv = *(const float4*)&W[(size_t)(bn + lrow) * DI_ + k0 + lcol];
        As[lcol + 0][lrow] = av.x; As[lcol + 1][lrow] = av.y;
        As[lcol + 2][lrow] = av.z; As[lcol + 3][lrow] = av.w;
        Ws[lcol + 0][lrow] = wv.x; Ws[lcol + 1][lrow] = wv.y;
        Ws[lcol + 2][lrow] = wv.z; Ws[lcol + 3][lrow] = wv.w;
        __syncthreads();

#pragma unroll
        for (int kk = 0; kk < K1_BK; kk++) {
            float a[4], w[4];
#pragma unroll
            for (int i = 0; i < 4; i++) a[i] = As[kk][ty * 4 + i];
#pragma unroll
            for (int j = 0; j < 4; j++) w[j] = Ws[kk][tx * 4 + j];
#pragma unroll
            for (int i = 0; i < 4; i++)
#pragma unroll
                for (int j = 0; j < 4; j++)
                    acc[i][j] = fmaf(a[i], w[j], acc[i][j]);
        }
        __syncthreads();
    }

    const int ncol = bn + tx * 4;
#pragma unroll
    for (int i = 0; i < 4; i++) {
        const int m = bm + ty * 4 + i;
        float4 o;
        o.x = acc[i][0]; o.y = acc[i][1]; o.z = acc[i][2]; o.w = acc[i][3];
        *(float4*)&Out[(size_t)m * DM_ + ncol] = o;
    }
}

// ============================================================================
extern "C" void kernel_launch(void* const* d_in, const int* in_sizes, int n_in,
                              void* d_out, int out_size)
{
    const float* x         = (const float*)d_in[0];
    const float* W_in      = (const float*)d_in[1];
    const float* x_proj_w  = (const float*)d_in[2];
    const float* dt_proj_w = (const float*)d_in[3];
    const float* dt_proj_b = (const float*)d_in[4];
    const float* A_logs    = (const float*)d_in[5];
    const float* Ds        = (const float*)d_in[6];
    const float* ln_gamma  = (const float*)d_in[7];
    const float* ln_beta   = (const float*)d_in[8];
    const float* W_out     = (const float*)d_in[9];
    float* out = (float*)d_out;

    float *u, *z, *delta, *bs, *cs, *y, *yln;
    cudaGetSymbolAddress((void**)&u, g_u);
    cudaGetSymbolAddress((void**)&z, g_z);
    cudaGetSymbolAddress((void**)&delta, g_delta);
    cudaGetSymbolAddress((void**)&bs, g_Bs);
    cudaGetSymbolAddress((void**)&cs, g_Cs);
    cudaGetSymbolAddress((void**)&y, g_y);
    cudaGetSymbolAddress((void**)&yln, g_yln);

    dim3 g1(M_ / K1_BM, NXZ_ / K1_BN);
    k1_gemm_silu<<<g1, 256>>>(x, W_in, u, z);

    k2_proj<<<M_ / K2_ROWS, 256>>>(u, x_proj_w, dt_proj_w, dt_proj_b,
                                   delta, bs, cs);

    k3_scan<<<(B_ * DI_ * 16) / 256, 256>>>(delta, u, bs, cs, A_logs, Ds, y);

    k4a_ln<<<M_ / 8, 256>>>(y, z, ln_gamma, ln_beta, yln);

    dim3 g4(M_ / K1_BM, DM_ / K1_BN);
    k4b_gemm<<<g4, 256>>>(yln, W_out, out);
}